// round 2
// baseline (speedup 1.0000x reference)
#include <cuda_runtime.h>
#include <cuda_bf16.h>
#include <cstdint>
#include <cstddef>

#define H 64
#define NG 100000
#define ND 30000

// ---------------- scratch (static device globals; no allocation) ----------------
__device__ float g_msum_d [ND * H];   // layer-1 aggregation into disease
__device__ float g_msum_g [NG * H];   // layer-1 aggregation into gene
__device__ float g_msum_d2[ND * H];   // layer-2 aggregation into disease
__device__ float g_msum_g2[NG * H];   // layer-2 aggregation into gene
__device__ float g_cnt_d  [ND];
__device__ float g_cnt_g  [NG];
__device__ float g_h_d    [ND * H];
__device__ float g_h_g    [NG * H];
__device__ float g_h_d2   [ND * H];
__device__ float g_h_g2   [NG * H];

// ---------------- zero the accumulators (float4 stores) ----------------
__global__ __launch_bounds__(256) void zero_kernel() {
    int i = blockIdx.x * blockDim.x + threadIdx.x;
    int stride = gridDim.x * blockDim.x;
    const int NDH4 = ND * H / 4;
    const int NGH4 = NG * H / 4;
    float4 z = make_float4(0.f, 0.f, 0.f, 0.f);
    float4* md  = (float4*)g_msum_d;
    float4* md2 = (float4*)g_msum_d2;
    float4* mg  = (float4*)g_msum_g;
    float4* mg2 = (float4*)g_msum_g2;
    for (int k = i; k < NDH4; k += stride) { md[k] = z; md2[k] = z; }
    for (int k = i; k < NGH4; k += stride) { mg[k] = z; mg2[k] = z; }
    for (int k = i; k < ND; k += stride) g_cnt_d[k] = 0.f;
    for (int k = i; k < NG; k += stride) g_cnt_g[k] = 0.f;
}

// ---------------- bidirectional edge scatter-add ----------------
// One warp per edge. Lanes 0-15: xsrc[s] -> acc_d[d]; lanes 16-31: xdst[d] -> acc_g[s].
__global__ __launch_bounds__(256) void scatter_kernel(
    const float* __restrict__ xsrc, const float* __restrict__ xdst,
    const int*   __restrict__ esrc, const int*   __restrict__ edst,
    float* __restrict__ acc_d, float* __restrict__ acc_g,
    float* __restrict__ cnt_d, float* __restrict__ cnt_g,
    int ne, int do_cnt)
{
    int w    = (blockIdx.x * blockDim.x + threadIdx.x) >> 5;
    int lane = threadIdx.x & 31;
    if (w >= ne) return;
    int s = __ldg(esrc + w);
    int d = __ldg(edst + w);
    if (lane < 16) {
        float4 v = __ldg((const float4*)(xsrc + (size_t)s * H) + lane);
        float* p = acc_d + (size_t)d * H + lane * 4;
        atomicAdd(p + 0, v.x);
        atomicAdd(p + 1, v.y);
        atomicAdd(p + 2, v.z);
        atomicAdd(p + 3, v.w);
        if (do_cnt && lane == 0) atomicAdd(cnt_d + d, 1.0f);
    } else {
        int c = lane - 16;
        float4 v = __ldg((const float4*)(xdst + (size_t)d * H) + c);
        float* p = acc_g + (size_t)s * H + c * 4;
        atomicAdd(p + 0, v.x);
        atomicAdd(p + 1, v.y);
        atomicAdd(p + 2, v.z);
        atomicAdd(p + 3, v.w);
        if (do_cnt && c == 0) atomicAdd(cnt_g + s, 1.0f);
    }
}

// ---------------- fused SAGE linear: out = (msum/max(cnt,1)) @ Wl + x @ Wr + b ----------------
// Treated as a [n x 128] @ [128 x 64] GEMM via phase loop. 64x64 tile, 4x4 microtile.
template<bool RELU>
__global__ __launch_bounds__(256) void sage_linear_kernel(
    const float* __restrict__ msum, const float* __restrict__ cnt,
    const float* __restrict__ xdst,
    const float* __restrict__ wl,   const float* __restrict__ wr,
    const float* __restrict__ bias,
    float* __restrict__ out, int n)
{
    __shared__ float sA[64][68];   // sA[r][k], row padded to 68 (16B-aligned rows)
    __shared__ float sW[64][64];   // sW[k][j]

    int t  = threadIdx.x;
    int tx = t & 15;        // col group: cols tx*4 .. tx*4+3
    int ty = t >> 4;        // row group: rows ty*4 .. ty*4+3
    int row0 = blockIdx.x * 64;

    float acc[4][4];
#pragma unroll
    for (int j = 0; j < 4; j++) {
        float b = __ldg(bias + tx * 4 + j);
#pragma unroll
        for (int i = 0; i < 4; i++) acc[i][j] = b;
    }

#pragma unroll
    for (int phase = 0; phase < 2; phase++) {
        const float* A = (phase == 0) ? msum : xdst;
        const float* W = (phase == 0) ? wl   : wr;

        __syncthreads();  // protect shared reuse from previous phase's compute

        // load W tile (4096 floats, contiguous copy)
#pragma unroll
        for (int i = 0; i < 4; i++) {
            int idx = t + i * 256;   // float4 index 0..1023
            ((float4*)&sW[0][0])[idx] = __ldg((const float4*)W + idx);
        }
        // load A tile (64 rows x 64 cols), normalize by count in phase 0
#pragma unroll
        for (int i = 0; i < 4; i++) {
            int idx = t + i * 256;       // float4 index
            int r   = idx >> 4;          // 0..63
            int k4  = idx & 15;
            int row = row0 + r;
            float4 v = make_float4(0.f, 0.f, 0.f, 0.f);
            if (row < n) {
                v = __ldg((const float4*)(A + (size_t)row * H) + k4);
                if (phase == 0) {
                    float inv = 1.0f / fmaxf(__ldg(cnt + row), 1.0f);
                    v.x *= inv; v.y *= inv; v.z *= inv; v.w *= inv;
                }
            }
            *(float4*)&sA[r][k4 * 4] = v;
        }
        __syncthreads();

#pragma unroll
        for (int k = 0; k < 64; k++) {
            float4 w4 = *(const float4*)&sW[k][tx * 4];
            float a0 = sA[ty * 4 + 0][k];
            float a1 = sA[ty * 4 + 1][k];
            float a2 = sA[ty * 4 + 2][k];
            float a3 = sA[ty * 4 + 3][k];
            acc[0][0] += a0 * w4.x; acc[0][1] += a0 * w4.y; acc[0][2] += a0 * w4.z; acc[0][3] += a0 * w4.w;
            acc[1][0] += a1 * w4.x; acc[1][1] += a1 * w4.y; acc[1][2] += a1 * w4.z; acc[1][3] += a1 * w4.w;
            acc[2][0] += a2 * w4.x; acc[2][1] += a2 * w4.y; acc[2][2] += a2 * w4.z; acc[2][3] += a2 * w4.w;
            acc[3][0] += a3 * w4.x; acc[3][1] += a3 * w4.y; acc[3][2] += a3 * w4.z; acc[3][3] += a3 * w4.w;
        }
    }

#pragma unroll
    for (int i = 0; i < 4; i++) {
        int row = row0 + ty * 4 + i;
        if (row < n) {
            float4 o = make_float4(acc[i][0], acc[i][1], acc[i][2], acc[i][3]);
            if (RELU) {
                o.x = fmaxf(o.x, 0.f); o.y = fmaxf(o.y, 0.f);
                o.z = fmaxf(o.z, 0.f); o.w = fmaxf(o.w, 0.f);
            }
            ((float4*)(out + (size_t)row * H))[tx] = o;
        }
    }
}

// ---------------- label-edge dot product ----------------
// One warp per label edge: lane loads float2 from each side, warp-reduce.
__global__ __launch_bounds__(256) void dot_kernel(
    const float* __restrict__ hg, const float* __restrict__ hd,
    const int* __restrict__ lsrc, const int* __restrict__ ldst,
    float* __restrict__ out, int nl)
{
    int w    = (blockIdx.x * blockDim.x + threadIdx.x) >> 5;
    int lane = threadIdx.x & 31;
    if (w >= nl) return;
    int gs = __ldg(lsrc + w);
    int dd = __ldg(ldst + w);
    float2 a = __ldg((const float2*)(hg + (size_t)gs * H) + lane);
    float2 b = __ldg((const float2*)(hd + (size_t)dd * H) + lane);
    float s = a.x * b.x + a.y * b.y;
#pragma unroll
    for (int off = 16; off > 0; off >>= 1)
        s += __shfl_xor_sync(0xFFFFFFFFu, s, off);
    if (lane == 0) out[w] = s;
}

// ---------------- launch ----------------
extern "C" void kernel_launch(void* const* d_in, const int* in_sizes, int n_in,
                              void* d_out, int out_size)
{
    // setup_inputs dict order
    const float* gene_emb    = (const float*)d_in[0];
    const float* disease_emb = (const float*)d_in[1];
    const float* w1_gd_l = (const float*)d_in[2];
    const float* w1_gd_r = (const float*)d_in[3];
    const float* w1_dg_l = (const float*)d_in[4];
    const float* w1_dg_r = (const float*)d_in[5];
    const float* w2_gd_l = (const float*)d_in[6];
    const float* w2_gd_r = (const float*)d_in[7];
    const float* w2_dg_l = (const float*)d_in[8];
    const float* w2_dg_r = (const float*)d_in[9];
    const float* b1_gd = (const float*)d_in[10];
    const float* b1_dg = (const float*)d_in[11];
    const float* b2_gd = (const float*)d_in[12];
    const float* b2_dg = (const float*)d_in[13];
    const int* esrc = (const int*)d_in[14];
    const int* edst = (const int*)d_in[15];
    const int* lsrc = (const int*)d_in[16];
    const int* ldst = (const int*)d_in[17];
    float* out = (float*)d_out;

    int ne = in_sizes[14];
    int nl = in_sizes[16];

    float *msum_d, *msum_g, *msum_d2, *msum_g2, *cnt_d, *cnt_g;
    float *h_d, *h_g, *h_d2, *h_g2;
    cudaGetSymbolAddress((void**)&msum_d,  g_msum_d);
    cudaGetSymbolAddress((void**)&msum_g,  g_msum_g);
    cudaGetSymbolAddress((void**)&msum_d2, g_msum_d2);
    cudaGetSymbolAddress((void**)&msum_g2, g_msum_g2);
    cudaGetSymbolAddress((void**)&cnt_d,   g_cnt_d);
    cudaGetSymbolAddress((void**)&cnt_g,   g_cnt_g);
    cudaGetSymbolAddress((void**)&h_d,     g_h_d);
    cudaGetSymbolAddress((void**)&h_g,     g_h_g);
    cudaGetSymbolAddress((void**)&h_d2,    g_h_d2);
    cudaGetSymbolAddress((void**)&h_g2,    g_h_g2);

    // 1) zero accumulators
    zero_kernel<<<4096, 256>>>();

    // 2) layer-1 aggregation (both directions, with counts)
    scatter_kernel<<<(ne + 7) / 8, 256>>>(gene_emb, disease_emb, esrc, edst,
                                          msum_d, msum_g, cnt_d, cnt_g, ne, 1);

    // 3) layer-1 linears (+ReLU)
    sage_linear_kernel<true><<<(ND + 63) / 64, 256>>>(msum_d, cnt_d, disease_emb,
                                                      w1_gd_l, w1_gd_r, b1_gd, h_d, ND);
    sage_linear_kernel<true><<<(NG + 63) / 64, 256>>>(msum_g, cnt_g, gene_emb,
                                                      w1_dg_l, w1_dg_r, b1_dg, h_g, NG);

    // 4) layer-2 aggregation (counts already computed — identical edge set)
    scatter_kernel<<<(ne + 7) / 8, 256>>>(h_g, h_d, esrc, edst,
                                          msum_d2, msum_g2, cnt_d, cnt_g, ne, 0);

    // 5) layer-2 linears (no activation)
    sage_linear_kernel<false><<<(ND + 63) / 64, 256>>>(msum_d2, cnt_d, h_d,
                                                       w2_gd_l, w2_gd_r, b2_gd, h_d2, ND);
    sage_linear_kernel<false><<<(NG + 63) / 64, 256>>>(msum_g2, cnt_g, h_g,
                                                       w2_dg_l, w2_dg_r, b2_dg, h_g2, NG);

    // 6) classifier dot products
    dot_kernel<<<(nl + 7) / 8, 256>>>(h_g2, h_d2, lsrc, ldst, out, nl);
}

// round 6
// speedup vs baseline: 1.5929x; 1.5929x over previous
#include <cuda_runtime.h>
#include <cuda_bf16.h>
#include <cstdint>
#include <cstddef>

#define H 64
#define NG 100000
#define ND 30000

// ---------------- scratch (static device globals; no allocation) ----------------
__device__ float g_msum_d [ND * H];   // layer-1 aggregation into disease
__device__ float g_msum_g [NG * H];   // layer-1 aggregation into gene
__device__ float g_msum_d2[ND * H];   // layer-2 aggregation into disease
__device__ float g_msum_g2[NG * H];   // layer-2 aggregation into gene
__device__ float g_cnt_d  [ND];
__device__ float g_cnt_g  [NG];
__device__ float g_h_d    [ND * H];
__device__ float g_h_g    [NG * H];
__device__ float g_h_d2   [ND * H];
__device__ float g_h_g2   [NG * H];

// Vectorized 128-bit float reduction to global memory (sm_90a+ PTX, REDG.128 on sm_103a).
__device__ __forceinline__ void red_add_v4(float* p, float4 v) {
    asm volatile("red.global.add.v4.f32 [%0], {%1, %2, %3, %4};"
                 :: "l"(p), "f"(v.x), "f"(v.y), "f"(v.z), "f"(v.w)
                 : "memory");
}

// ---------------- zero the accumulators (float4 stores) ----------------
__global__ __launch_bounds__(256) void zero_kernel() {
    int i = blockIdx.x * blockDim.x + threadIdx.x;
    int stride = gridDim.x * blockDim.x;
    const int NDH4 = ND * H / 4;
    const int NGH4 = NG * H / 4;
    float4 z = make_float4(0.f, 0.f, 0.f, 0.f);
    float4* md  = (float4*)g_msum_d;
    float4* md2 = (float4*)g_msum_d2;
    float4* mg  = (float4*)g_msum_g;
    float4* mg2 = (float4*)g_msum_g2;
    for (int k = i; k < NDH4; k += stride) { md[k] = z; md2[k] = z; }
    for (int k = i; k < NGH4; k += stride) { mg[k] = z; mg2[k] = z; }
    for (int k = i; k < ND; k += stride) g_cnt_d[k] = 0.f;
    for (int k = i; k < NG; k += stride) g_cnt_g[k] = 0.f;
}

// ---------------- bidirectional edge scatter-add (vectorized RED) ----------------
// One warp per edge. Lanes 0-15: xsrc[s] -> acc_d[d]; lanes 16-31: xdst[d] -> acc_g[s].
// Each lane moves one float4 chunk with a single red.global.add.v4.f32.
__global__ __launch_bounds__(256) void scatter_kernel(
    const float* __restrict__ xsrc, const float* __restrict__ xdst,
    const int*   __restrict__ esrc, const int*   __restrict__ edst,
    float* __restrict__ acc_d, float* __restrict__ acc_g,
    float* __restrict__ cnt_d, float* __restrict__ cnt_g,
    int ne, int do_cnt)
{
    int w    = (blockIdx.x * blockDim.x + threadIdx.x) >> 5;
    int lane = threadIdx.x & 31;
    if (w >= ne) return;
    int s = __ldg(esrc + w);
    int d = __ldg(edst + w);
    if (lane < 16) {
        float4 v = __ldg((const float4*)(xsrc + (size_t)s * H) + lane);
        red_add_v4(acc_d + (size_t)d * H + lane * 4, v);
        if (do_cnt && lane == 0) atomicAdd(cnt_d + d, 1.0f);
    } else {
        int c = lane - 16;
        float4 v = __ldg((const float4*)(xdst + (size_t)d * H) + c);
        red_add_v4(acc_g + (size_t)s * H + c * 4, v);
        if (do_cnt && c == 0) atomicAdd(cnt_g + s, 1.0f);
    }
}

// ---------------- fused SAGE linear: out = (msum/max(cnt,1)) @ Wl + x @ Wr + b ----------------
// Treated as a [n x 128] @ [128 x 64] GEMM via phase loop. 64x64 tile, 4x4 microtile.
template<bool RELU>
__global__ __launch_bounds__(256) void sage_linear_kernel(
    const float* __restrict__ msum, const float* __restrict__ cnt,
    const float* __restrict__ xdst,
    const float* __restrict__ wl,   const float* __restrict__ wr,
    const float* __restrict__ bias,
    float* __restrict__ out, int n)
{
    __shared__ float sA[64][68];   // sA[r][k], row padded to 68 (16B-aligned rows)
    __shared__ float sW[64][64];   // sW[k][j]

    int t  = threadIdx.x;
    int tx = t & 15;        // col group: cols tx*4 .. tx*4+3
    int ty = t >> 4;        // row group: rows ty*4 .. ty*4+3
    int row0 = blockIdx.x * 64;

    float acc[4][4];
#pragma unroll
    for (int j = 0; j < 4; j++) {
        float b = __ldg(bias + tx * 4 + j);
#pragma unroll
        for (int i = 0; i < 4; i++) acc[i][j] = b;
    }

#pragma unroll
    for (int phase = 0; phase < 2; phase++) {
        const float* A = (phase == 0) ? msum : xdst;
        const float* W = (phase == 0) ? wl   : wr;

        __syncthreads();  // protect shared reuse from previous phase's compute

        // load W tile (4096 floats, contiguous copy)
#pragma unroll
        for (int i = 0; i < 4; i++) {
            int idx = t + i * 256;   // float4 index 0..1023
            ((float4*)&sW[0][0])[idx] = __ldg((const float4*)W + idx);
        }
        // load A tile (64 rows x 64 cols), normalize by count in phase 0
#pragma unroll
        for (int i = 0; i < 4; i++) {
            int idx = t + i * 256;       // float4 index
            int r   = idx >> 4;          // 0..63
            int k4  = idx & 15;
            int row = row0 + r;
            float4 v = make_float4(0.f, 0.f, 0.f, 0.f);
            if (row < n) {
                v = __ldg((const float4*)(A + (size_t)row * H) + k4);
                if (phase == 0) {
                    float inv = 1.0f / fmaxf(__ldg(cnt + row), 1.0f);
                    v.x *= inv; v.y *= inv; v.z *= inv; v.w *= inv;
                }
            }
            *(float4*)&sA[r][k4 * 4] = v;
        }
        __syncthreads();

#pragma unroll
        for (int k = 0; k < 64; k++) {
            float4 w4 = *(const float4*)&sW[k][tx * 4];
            float a0 = sA[ty * 4 + 0][k];
            float a1 = sA[ty * 4 + 1][k];
            float a2 = sA[ty * 4 + 2][k];
            float a3 = sA[ty * 4 + 3][k];
            acc[0][0] += a0 * w4.x; acc[0][1] += a0 * w4.y; acc[0][2] += a0 * w4.z; acc[0][3] += a0 * w4.w;
            acc[1][0] += a1 * w4.x; acc[1][1] += a1 * w4.y; acc[1][2] += a1 * w4.z; acc[1][3] += a1 * w4.w;
            acc[2][0] += a2 * w4.x; acc[2][1] += a2 * w4.y; acc[2][2] += a2 * w4.z; acc[2][3] += a2 * w4.w;
            acc[3][0] += a3 * w4.x; acc[3][1] += a3 * w4.y; acc[3][2] += a3 * w4.z; acc[3][3] += a3 * w4.w;
        }
    }

#pragma unroll
    for (int i = 0; i < 4; i++) {
        int row = row0 + ty * 4 + i;
        if (row < n) {
            float4 o = make_float4(acc[i][0], acc[i][1], acc[i][2], acc[i][3]);
            if (RELU) {
                o.x = fmaxf(o.x, 0.f); o.y = fmaxf(o.y, 0.f);
                o.z = fmaxf(o.z, 0.f); o.w = fmaxf(o.w, 0.f);
            }
            ((float4*)(out + (size_t)row * H))[tx] = o;
        }
    }
}

// ---------------- label-edge dot product ----------------
// One warp per label edge: lane loads float2 from each side, warp-reduce.
__global__ __launch_bounds__(256) void dot_kernel(
    const float* __restrict__ hg, const float* __restrict__ hd,
    const int* __restrict__ lsrc, const int* __restrict__ ldst,
    float* __restrict__ out, int nl)
{
    int w    = (blockIdx.x * blockDim.x + threadIdx.x) >> 5;
    int lane = threadIdx.x & 31;
    if (w >= nl) return;
    int gs = __ldg(lsrc + w);
    int dd = __ldg(ldst + w);
    float2 a = __ldg((const float2*)(hg + (size_t)gs * H) + lane);
    float2 b = __ldg((const float2*)(hd + (size_t)dd * H) + lane);
    float s = a.x * b.x + a.y * b.y;
#pragma unroll
    for (int off = 16; off > 0; off >>= 1)
        s += __shfl_xor_sync(0xFFFFFFFFu, s, off);
    if (lane == 0) out[w] = s;
}

// ---------------- launch ----------------
extern "C" void kernel_launch(void* const* d_in, const int* in_sizes, int n_in,
                              void* d_out, int out_size)
{
    // setup_inputs dict order
    const float* gene_emb    = (const float*)d_in[0];
    const float* disease_emb = (const float*)d_in[1];
    const float* w1_gd_l = (const float*)d_in[2];
    const float* w1_gd_r = (const float*)d_in[3];
    const float* w1_dg_l = (const float*)d_in[4];
    const float* w1_dg_r = (const float*)d_in[5];
    const float* w2_gd_l = (const float*)d_in[6];
    const float* w2_gd_r = (const float*)d_in[7];
    const float* w2_dg_l = (const float*)d_in[8];
    const float* w2_dg_r = (const float*)d_in[9];
    const float* b1_gd = (const float*)d_in[10];
    const float* b1_dg = (const float*)d_in[11];
    const float* b2_gd = (const float*)d_in[12];
    const float* b2_dg = (const float*)d_in[13];
    const int* esrc = (const int*)d_in[14];
    const int* edst = (const int*)d_in[15];
    const int* lsrc = (const int*)d_in[16];
    const int* ldst = (const int*)d_in[17];
    float* out = (float*)d_out;

    int ne = in_sizes[14];
    int nl = in_sizes[16];

    float *msum_d, *msum_g, *msum_d2, *msum_g2, *cnt_d, *cnt_g;
    float *h_d, *h_g, *h_d2, *h_g2;
    cudaGetSymbolAddress((void**)&msum_d,  g_msum_d);
    cudaGetSymbolAddress((void**)&msum_g,  g_msum_g);
    cudaGetSymbolAddress((void**)&msum_d2, g_msum_d2);
    cudaGetSymbolAddress((void**)&msum_g2, g_msum_g2);
    cudaGetSymbolAddress((void**)&cnt_d,   g_cnt_d);
    cudaGetSymbolAddress((void**)&cnt_g,   g_cnt_g);
    cudaGetSymbolAddress((void**)&h_d,     g_h_d);
    cudaGetSymbolAddress((void**)&h_g,     g_h_g);
    cudaGetSymbolAddress((void**)&h_d2,    g_h_d2);
    cudaGetSymbolAddress((void**)&h_g2,    g_h_g2);

    // 1) zero accumulators
    zero_kernel<<<4096, 256>>>();

    // 2) layer-1 aggregation (both directions, with counts)
    scatter_kernel<<<(ne + 7) / 8, 256>>>(gene_emb, disease_emb, esrc, edst,
                                          msum_d, msum_g, cnt_d, cnt_g, ne, 1);

    // 3) layer-1 linears (+ReLU)
    sage_linear_kernel<true><<<(ND + 63) / 64, 256>>>(msum_d, cnt_d, disease_emb,
                                                      w1_gd_l, w1_gd_r, b1_gd, h_d, ND);
    sage_linear_kernel<true><<<(NG + 63) / 64, 256>>>(msum_g, cnt_g, gene_emb,
                                                      w1_dg_l, w1_dg_r, b1_dg, h_g, NG);

    // 4) layer-2 aggregation (counts already computed — identical edge set)
    scatter_kernel<<<(ne + 7) / 8, 256>>>(h_g, h_d, esrc, edst,
                                          msum_d2, msum_g2, cnt_d, cnt_g, ne, 0);

    // 5) layer-2 linears (no activation)
    sage_linear_kernel<false><<<(ND + 63) / 64, 256>>>(msum_d2, cnt_d, h_d,
                                                       w2_gd_l, w2_gd_r, b2_gd, h_d2, ND);
    sage_linear_kernel<false><<<(NG + 63) / 64, 256>>>(msum_g2, cnt_g, h_g,
                                                       w2_dg_l, w2_dg_r, b2_dg, h_g2, NG);

    // 6) classifier dot products
    dot_kernel<<<(nl + 7) / 8, 256>>>(h_g2, h_d2, lsrc, ldst, out, nl);
}